// round 2
// baseline (speedup 1.0000x reference)
#include <cuda_runtime.h>
#include <cstdint>

// GrokkingSNN: B=32768, hidden=512, p=97, 15 steps.
// Algebraic restructure:
//   P1[v,j] = sum_k E[v,k]*W1[j,k]         (s=0 half)
//   P2[v,j] = sum_k E[v,k]*W1[j,512+k]     (s=1 half)
//   cur1[b,j] = P1[x0,j] + P2[x1,j] + b1[j]
//   Only 97*97=9409 distinct (x0,x1) pairs -> simulate per pair.
//   mem2 = (sum_t beta2^{15-t} spk_t) @ W2.T + b2 * G,  G = sum beta2^k
//   Then scatter per-pair result rows to the 32768 output rows.

#define HIDDEN 512
#define PDIM 97
#define NPAIR (PDIM * PDIM)   // 9409
#define NSTEPS 15
#define UPITCH 104

#define SPITCH 68   // Ssm pitch (floats): 512 rows x 68 (64 pairs + pad, float4 aligned)
#define WPITCH 66   // W2 chunk pitch
#define KC 64       // K-chunk for W2 staging

__device__ float g_P[2 * PDIM * HIDDEN];    // [s][v][j]
__device__ float g_U[NPAIR * UPITCH];       // per-pair output rows (+bias)

// ---------------------------------------------------------------------------
// Kernel A: P[s][v][j] = sum_k E[v][k] * W1[j][s*512+k]
// grid (4 j-tiles, 13 v-tiles, 2 s), 128 threads. 8 E-rows staged in smem.
// ---------------------------------------------------------------------------
__global__ void __launch_bounds__(128) precompute_kernel(
    const float* __restrict__ E, const float* __restrict__ W1)
{
    __shared__ float e[8][HIDDEN];
    const int jt = blockIdx.x, vt = blockIdx.y, s = blockIdx.z;
    const int vbase = vt * 8;

    for (int idx = threadIdx.x; idx < 8 * HIDDEN; idx += 128) {
        int vv = idx >> 9;
        int k  = idx & 511;
        int v  = vbase + vv;
        e[vv][k] = (v < PDIM) ? E[v * HIDDEN + k] : 0.0f;
    }
    __syncthreads();

    const int j = jt * 128 + threadIdx.x;
    const float4* wrow =
        reinterpret_cast<const float4*>(W1 + (size_t)j * (2 * HIDDEN) + s * HIDDEN);

    float acc[8];
#pragma unroll
    for (int v = 0; v < 8; v++) acc[v] = 0.0f;

#pragma unroll 4
    for (int k4 = 0; k4 < HIDDEN / 4; k4++) {
        float4 w = wrow[k4];
        int k = k4 * 4;
#pragma unroll
        for (int v = 0; v < 8; v++) {
            acc[v] = fmaf(e[v][k + 0], w.x, acc[v]);
            acc[v] = fmaf(e[v][k + 1], w.y, acc[v]);
            acc[v] = fmaf(e[v][k + 2], w.z, acc[v]);
            acc[v] = fmaf(e[v][k + 3], w.w, acc[v]);
        }
    }

#pragma unroll
    for (int v = 0; v < 8; v++) {
        int vg = vbase + v;
        if (vg < PDIM) g_P[(s * PDIM + vg) * HIDDEN + j] = acc[v];
    }
}

// ---------------------------------------------------------------------------
// Kernel B: per-pair 15-step LIF simulation -> weighted spike sums S,
// then U = S @ W2.T + b2*G.  148 blocks x 64 pairs, 256 threads.
// Phase 1: thread owns pair q = tid&63, h-rows tid>>6 + 4i, ILP=4.
// Phase 2: register-tiled GEMM (4 pairs x 7 p per thread), W2 chunked in smem.
// ---------------------------------------------------------------------------
__global__ void __launch_bounds__(256, 1) pair_kernel(
    const float* __restrict__ b1, const float* __restrict__ W2,
    const float* __restrict__ b2, const float* __restrict__ pbeta1,
    const float* __restrict__ pbeta2, const float* __restrict__ pthr1)
{
    extern __shared__ float sm[];
    float* Ssm = sm;                       // [512][SPITCH]
    float* W2s = sm + 512 * SPITCH;        // [112][WPITCH] (rows >=97 unused)

    const float beta1 = fminf(fmaxf(__ldg(pbeta1), 0.1f), 0.9f);
    const float beta2 = fminf(fmaxf(__ldg(pbeta2), 0.1f), 0.9f);
    const float thr1  = fmaxf(__ldg(pthr1), 0.1f);

    const int tid = threadIdx.x;

    // ---------------- phase 1: simulate 64 pairs x 512 h ----------------
    {
        const int q  = tid & 63;
        const int hb = tid >> 6;   // 0..3
        int pp = blockIdx.x * 64 + q;
        if (pp >= NPAIR) pp = 0;   // junk lanes; never stored in phase 2
        const int a = pp / PDIM;
        const int b = pp - a * PDIM;
        const float* p1 = g_P + a * HIDDEN;                // s=0 plane
        const float* p2 = g_P + (PDIM + b) * HIDDEN;       // s=1 plane

        for (int o = 0; o < 32; o++) {
            float c[4], m[4], S[4];
            bool  sp[4];
#pragma unroll
            for (int u = 0; u < 4; u++) {
                int h = hb + o * 16 + u * 4;
                c[u] = __ldg(p1 + h) + __ldg(p2 + h) + __ldg(b1 + h);
                m[u] = 0.0f; S[u] = 0.0f; sp[u] = false;
            }
#pragma unroll
            for (int t = 0; t < NSTEPS; t++) {
#pragma unroll
                for (int u = 0; u < 4; u++) {
                    // mem1 = beta1*mem1 + cur1 - reset*thr1  (reference op order)
                    float mm = __fadd_rn(__fmul_rn(beta1, m[u]), c[u]);
                    if (sp[u]) mm = __fsub_rn(mm, thr1);
                    sp[u] = (mm > thr1);
                    m[u] = mm;
                    // weighted spike accumulation: S = beta2*S + spk
                    S[u] = fmaf(beta2, S[u], sp[u] ? 1.0f : 0.0f);
                }
            }
#pragma unroll
            for (int u = 0; u < 4; u++) {
                int h = hb + o * 16 + u * 4;
                Ssm[h * SPITCH + q] = S[u];
            }
        }
    }

    // ---------------- phase 2: U = S @ W2.T ----------------
    const int tx = tid & 15;   // pair tile
    const int ty = tid >> 4;   // p tile

    float acc[4][7];
#pragma unroll
    for (int j = 0; j < 4; j++)
#pragma unroll
        for (int i = 0; i < 7; i++) acc[j][i] = 0.0f;

    for (int kb = 0; kb < HIDDEN / KC; kb++) {
        __syncthreads();   // first iter: phase-1 done; later: previous chunk consumed
        for (int idx = tid; idx < PDIM * KC; idx += 256) {
            int p = idx >> 6;
            int k = idx & 63;
            W2s[p * WPITCH + k] = __ldg(W2 + p * HIDDEN + kb * KC + k);
        }
        __syncthreads();

#pragma unroll 4
        for (int k = 0; k < KC; k++) {
            int kg = kb * KC + k;
            float4 sv = *reinterpret_cast<const float4*>(Ssm + kg * SPITCH + tx * 4);
            float w[7];
#pragma unroll
            for (int i = 0; i < 7; i++) w[i] = W2s[(ty * 7 + i) * WPITCH + k];
#pragma unroll
            for (int i = 0; i < 7; i++) {
                acc[0][i] = fmaf(sv.x, w[i], acc[0][i]);
                acc[1][i] = fmaf(sv.y, w[i], acc[1][i]);
                acc[2][i] = fmaf(sv.z, w[i], acc[2][i]);
                acc[3][i] = fmaf(sv.w, w[i], acc[3][i]);
            }
        }
    }

    // G = sum_{k=0..14} beta2^k via same recursion as mem2
    float G = 0.0f;
#pragma unroll
    for (int t = 0; t < NSTEPS; t++) G = __fadd_rn(__fmul_rn(beta2, G), 1.0f);

    const int ppb = blockIdx.x * 64 + tx * 4;
#pragma unroll
    for (int j = 0; j < 4; j++) {
        int pp = ppb + j;
        if (pp < NPAIR) {
#pragma unroll
            for (int i = 0; i < 7; i++) {
                int p = ty * 7 + i;
                if (p < PDIM)
                    g_U[pp * UPITCH + p] = acc[j][i] + __ldg(b2 + p) * G;
            }
        }
    }
}

// ---------------------------------------------------------------------------
// Kernel C: out[b,:] = U[pair(b),:]. One warp per output row.
// ---------------------------------------------------------------------------
__global__ void __launch_bounds__(256) scatter_kernel(
    const int* __restrict__ x, float* __restrict__ out, int B)
{
    int warp = blockIdx.x * 8 + (threadIdx.x >> 5);
    int lane = threadIdx.x & 31;
    if (warp >= B) return;
    int x0 = __ldg(x + 2 * warp);
    int x1 = __ldg(x + 2 * warp + 1);
    const float* u = g_U + (size_t)(x0 * PDIM + x1) * UPITCH;
    float* o = out + (size_t)warp * PDIM;
#pragma unroll
    for (int j = 0; j < 3; j++) o[lane + 32 * j] = u[lane + 32 * j];
    if (lane == 0) o[96] = u[96];
}

// ---------------------------------------------------------------------------
extern "C" void kernel_launch(void* const* d_in, const int* in_sizes, int n_in,
                              void* d_out, int out_size)
{
    const int*   x     = (const int*)  d_in[0];
    const float* E     = (const float*)d_in[1];
    const float* W1    = (const float*)d_in[2];
    const float* b1    = (const float*)d_in[3];
    const float* W2    = (const float*)d_in[4];
    const float* b2    = (const float*)d_in[5];
    const float* beta1 = (const float*)d_in[6];
    const float* beta2 = (const float*)d_in[7];
    const float* thr1  = (const float*)d_in[8];
    // thr2 (d_in[9]) is unused in the forward pass (lif2 reset='none', output is mem2).

    const int B = in_sizes[0] / 2;

    const int smemB = (512 * SPITCH + 112 * WPITCH) * (int)sizeof(float); // 168832 B
    cudaFuncSetAttribute(pair_kernel, cudaFuncAttributeMaxDynamicSharedMemorySize, smemB);

    precompute_kernel<<<dim3(4, 13, 2), 128>>>(E, W1);
    pair_kernel<<<148, 256, smemB>>>(b1, W2, b2, beta1, beta2, thr1);
    scatter_kernel<<<(B + 7) / 8, 256>>>(x, (float*)d_out, B);
}